// round 16
// baseline (speedup 1.0000x reference)
#include <cuda_runtime.h>
#include <cuda_fp16.h>
#include <cstdint>
#include <cstddef>
#include <math.h>

#define NMAX 4096
#define DDIM 128
#define POS_W 2.0f
#define NEG_W 40.0f
#define MARGIN 0.1f
#define THRESH 0.5f

// ---------------- scratch (no allocations allowed) ----------------
__device__ unsigned short g_xhi[NMAX * DDIM];          // fp16 hi parts
__device__ unsigned short g_xlo[NMAX * DDIM];          // fp16 lo parts
__device__ int      g_lab[NMAX];
__device__ float    g_S[(size_t)NMAX * NMAX];          // upper-triangle tiles only
__device__ unsigned g_minpos[NMAX];
__device__ unsigned g_maxneg[NMAX];
__device__ float    g_psum[NMAX];
__device__ float    g_nsum[NMAX];
__device__ int      g_lflag;

__device__ __forceinline__ unsigned fenc(float f) {
    unsigned u = __float_as_uint(f);
    return (u & 0x80000000u) ? ~u : (u | 0x80000000u);
}
__device__ __forceinline__ float fdec(unsigned e) {
    unsigned u = (e & 0x80000000u) ? (e ^ 0x80000000u) : ~e;
    return __uint_as_float(u);
}

__device__ __forceinline__ uint32_t smem_u32(const void* p) {
    uint32_t a;
    asm("{ .reg .u64 t; cvta.to.shared.u64 t, %1; cvt.u32.u64 %0, t; }" : "=r"(a) : "l"(p));
    return a;
}

#define LDSM_X4(r, ad) \
    asm volatile("ldmatrix.sync.aligned.m8n8.x4.shared.b16 {%0,%1,%2,%3}, [%4];" \
        : "=r"((r)[0]), "=r"((r)[1]), "=r"((r)[2]), "=r"((r)[3]) : "r"(ad))

#define MMAF16(c, a, b) \
    asm volatile("mma.sync.aligned.m16n8k16.row.col.f32.f16.f16.f32 " \
        "{%0,%1,%2,%3}, {%4,%5,%6,%7}, {%8,%9}, {%0,%1,%2,%3};" \
        : "+f"((c)[0]), "+f"((c)[1]), "+f"((c)[2]), "+f"((c)[3]) \
        : "r"((a)[0]), "r"((a)[1]), "r"((a)[2]), "r"((a)[3]), "r"((b)[0]), "r"((b)[1]))

#define CP_ASYNC16(sa, ga) \
    asm volatile("cp.async.cg.shared.global [%0], [%1], 16;" :: "r"(sa), "l"(ga))
#define CP_COMMIT() asm volatile("cp.async.commit_group;" ::: "memory")
#define CP_WAIT0()  asm volatile("cp.async.wait_group 0;" ::: "memory")

template <int P>
__device__ __forceinline__ void cp_wait() {
    asm volatile("cp.async.wait_group %0;" :: "n"(P) : "memory");
}

// smem layout (bytes). 3 fp16 tiles [128][136] (272B stride, ldmatrix conflict-free)
#define TLD       136
#define TILE_B    (128 * TLD * 2)
#define OFF_LBLR  0
#define OFF_LBLC  512
#define OFF_AHI   1024
#define OFF_BHI   (OFF_AHI + TILE_B)
#define OFF_BLO   (OFF_BHI + TILE_B)
#define SMEM_TOTAL (OFF_BLO + TILE_B)
// epilogue overlays (on dead tiles): stage 67.6KB, then col min/max scoreboards
#define SLD2      132
#define OFF_STAGE OFF_AHI
#define OFF_CMN   (OFF_STAGE + 128 * SLD2 * 4)
#define OFF_CMX   (OFF_CMN + 128 * 33 * 4)

// k_tsum ring: 4 slots x 16 rows x 33 float4 (528B row stride)
#define TS_RING_BYTES (4 * 16 * 33 * 16)

__device__ __forceinline__ void split2h(float x, float y, uint32_t& hi, uint32_t& lo) {
    __half hx = __float2half_rn(x), hy = __float2half_rn(y);
    __half lx = __float2half_rn(x - __half2float(hx));
    __half ly = __float2half_rn(y - __half2float(hy));
    unsigned short a = *(unsigned short*)&hx, b = *(unsigned short*)&hy;
    unsigned short c = *(unsigned short*)&lx, d = *(unsigned short*)&ly;
    hi = (uint32_t)a | ((uint32_t)b << 16);
    lo = (uint32_t)c | ((uint32_t)d << 16);
}

__device__ __forceinline__ void tri_map(int t, int& bx, int& by) {
    bx = (int)((sqrtf(8.0f * (float)t + 1.0f) - 1.0f) * 0.5f);
    while ((bx + 1) * (bx + 2) / 2 <= t) bx++;
    while (bx * (bx + 1) / 2 > t) bx--;
    by = t - bx * (bx + 1) / 2;
}

// ---------------- small kernels ----------------
__global__ void k_detect(const int* __restrict__ lab32, int N) {
    __shared__ int s;
    if (threadIdx.x == 0) s = 0;
    __syncthreads();
    int any = 0;
    for (int i = 1 + 2 * (int)threadIdx.x; i < N; i += 2 * (int)blockDim.x)
        if (lab32[i] != 0) any = 1;
    if (any) atomicOr(&s, 1);
    __syncthreads();
    if (threadIdx.x == 0) g_lflag = s;
}

// fused: per-row L2 norm + fp16 split, plus label convert + per-row init
__global__ void k_prepnorm(const float* __restrict__ x, const void* __restrict__ labv, int N) {
    int warp = threadIdx.x >> 5, lane = threadIdx.x & 31;
    if (threadIdx.x < 8) {
        int i = blockIdx.x * 8 + threadIdx.x;
        if (i < N) {
            int v;
            if (g_lflag) v = ((const int*)labv)[i];
            else         v = (int)(((const long long*)labv)[i]);
            g_lab[i]    = v;
            g_minpos[i] = fenc(1e9f);
            g_maxneg[i] = fenc(-1e9f);
            g_psum[i]   = 0.f;
            g_nsum[i]   = 0.f;
        }
    }
    int row = blockIdx.x * 8 + warp;
    if (row >= N) return;
    float4 v = *(const float4*)(x + (size_t)row * DDIM + lane * 4);
    float ss = v.x * v.x + v.y * v.y + v.z * v.z + v.w * v.w;
#pragma unroll
    for (int o = 16; o > 0; o >>= 1) ss += __shfl_xor_sync(0xffffffffu, ss, o);
    float inv = 1.0f / sqrtf(ss);
    uint32_t h0, l0, h1, l1;
    split2h(v.x * inv, v.y * inv, h0, l0);
    split2h(v.z * inv, v.w * inv, h1, l1);
    *(uint2*)(g_xhi + (size_t)row * DDIM + lane * 4) = make_uint2(h0, h1);
    *(uint2*)(g_xlo + (size_t)row * DDIM + lane * 4) = make_uint2(l0, l1);
}

// ---------------- HMMA tile kernel: fp16 2-product (hh + hl) ----------------
__global__ __launch_bounds__(512, 1) void k_gemm_mma(int N) {
    extern __shared__ char smem[];
    uint32_t sb = smem_u32(smem);
    int* lblRow = (int*)(smem + OFF_LBLR);
    int* lblCol = (int*)(smem + OFF_LBLC);

    int tid = threadIdx.x, wid = tid >> 5, lane = tid & 31;

    int bx, by;
    tri_map(blockIdx.x, bx, by);
    int row0 = by * 128, col0 = bx * 128;
    bool diag = (bx == by);

    if (tid < 128) lblRow[tid] = g_lab[row0 + tid];
    else if (tid < 256) lblCol[tid - 128] = g_lab[col0 + tid - 128];

    // prologue: cp.async copies of precomputed fp16 tiles (A: hi; B: hi + lo)
    {
        int r = tid >> 2, ch = (tid & 3) * 32;
#pragma unroll
        for (int qq = 0; qq < 4; qq++) {
            int col = ch + qq * 8;
            uint32_t off = (uint32_t)(r * TLD + col) * 2u;
            CP_ASYNC16(sb + OFF_AHI + off, (const char*)(g_xhi + (size_t)(row0 + r) * DDIM + col));
            CP_ASYNC16(sb + OFF_BHI + off, (const char*)(g_xhi + (size_t)(col0 + r) * DDIM + col));
            CP_ASYNC16(sb + OFF_BLO + off, (const char*)(g_xlo + (size_t)(col0 + r) * DDIM + col));
        }
        CP_COMMIT();
        CP_WAIT0();
    }
    __syncthreads();

    // 16 warps -> 4 (m) x 4 (n); warp tile 32x32
    int warp_m = wid >> 2, warp_n = wid & 3;
    int m0 = warp_m * 32, n0 = warp_n * 32;
    int q = lane >> 2, tq = lane & 3;

    float acc[2][4][4];
#pragma unroll
    for (int i = 0; i < 2; i++)
#pragma unroll
        for (int j = 0; j < 4; j++)
#pragma unroll
            for (int r = 0; r < 4; r++) acc[i][j][r] = 0.f;

    int aRow = (lane & 7) + ((lane >> 3) & 1) * 8;
    int aColH = ((lane >> 4) & 1) * 8;
    int bRow = (lane & 7) + ((lane >> 4) & 1) * 8;
    int bColH = ((lane >> 3) & 1) * 8;

    uint32_t aHi = sb + OFF_AHI + (uint32_t)((m0 + aRow) * TLD + aColH) * 2u;
    uint32_t bHi = sb + OFF_BHI + (uint32_t)((n0 + bRow) * TLD + bColH) * 2u;
    uint32_t bLo = sb + OFF_BLO + (uint32_t)((n0 + bRow) * TLD + bColH) * 2u;

    uint32_t ah[2][8], bh[2][8], bl[2][8];

#define LOAD_STEP(B, K0) do {                                             \
        uint32_t ko = (uint32_t)(K0) * 2u;                                \
        LDSM_X4(&ah[B][0], aHi + ko);                                     \
        LDSM_X4(&ah[B][4], aHi + (uint32_t)(16 * TLD) * 2u + ko);         \
        LDSM_X4(&bh[B][0], bHi + ko);                                     \
        LDSM_X4(&bh[B][4], bHi + (uint32_t)(16 * TLD) * 2u + ko);         \
        LDSM_X4(&bl[B][0], bLo + ko);                                     \
        LDSM_X4(&bl[B][4], bLo + (uint32_t)(16 * TLD) * 2u + ko);         \
    } while (0)

    LOAD_STEP(0, 0);
#pragma unroll
    for (int s = 0; s < 8; s++) {
        int buf = s & 1;
        if (s < 7) {
            if (buf == 0) LOAD_STEP(1, (s + 1) * 16);
            else          LOAD_STEP(0, (s + 1) * 16);
        }
#pragma unroll
        for (int i = 0; i < 2; i++)
#pragma unroll
            for (int j = 0; j < 4; j++)
                MMAF16(acc[i][j], &ah[buf][4 * i], &bh[buf][2 * j]);   // hi*hi
#pragma unroll
        for (int i = 0; i < 2; i++)
#pragma unroll
            for (int j = 0; j < 4; j++)
                MMAF16(acc[i][j], &ah[buf][4 * i], &bl[buf][2 * j]);   // hi*lo
    }
#undef LOAD_STEP

    // ---- row stats from accumulators ----
#pragma unroll
    for (int i = 0; i < 2; i++) {
#pragma unroll
        for (int h = 0; h < 2; h++) {
            int rl = m0 + 16 * i + q + 8 * h;
            int gr = row0 + rl;
            int lr = lblRow[rl];
            float mn = 1e9f, mx = -1e9f;
#pragma unroll
            for (int j = 0; j < 4; j++) {
#pragma unroll
                for (int zz = 0; zz < 2; zz++) {
                    float s = acc[i][j][2 * h + zz];
                    int c = n0 + 8 * j + 2 * tq + zz;
                    if (lblCol[c] == lr) {
                        if (gr != col0 + c && s < mn) mn = s;
                    } else if (s > mx) mx = s;
                }
            }
            mn = fminf(mn, __shfl_xor_sync(0xffffffffu, mn, 1));
            mx = fmaxf(mx, __shfl_xor_sync(0xffffffffu, mx, 1));
            mn = fminf(mn, __shfl_xor_sync(0xffffffffu, mn, 2));
            mx = fmaxf(mx, __shfl_xor_sync(0xffffffffu, mx, 2));
            if (tq == 0) {
                atomicMin(&g_minpos[gr], fenc(mn));
                atomicMax(&g_maxneg[gr], fenc(mx));
            }
        }
    }

    // ---- overlay epilogue: stage S + col-stat scoreboards in dead tile smem ----
    __syncthreads();
    float* stage = (float*)(smem + OFF_STAGE);
    float* cmnS  = (float*)(smem + OFF_CMN);
    float* cmxS  = (float*)(smem + OFF_CMX);

#pragma unroll
    for (int i = 0; i < 2; i++) {
#pragma unroll
        for (int j = 0; j < 4; j++) {
#pragma unroll
            for (int h = 0; h < 2; h++) {
                int r = m0 + 16 * i + q + 8 * h;
                int c = n0 + 8 * j + 2 * tq;
                *(float2*)&stage[r * SLD2 + c] =
                    make_float2(acc[i][j][2 * h], acc[i][j][2 * h + 1]);
            }
        }
    }
    if (!diag) {
        int widx = warp_m * 8 + q;
#pragma unroll
        for (int j = 0; j < 4; j++) {
#pragma unroll
            for (int zz = 0; zz < 2; zz++) {
                int c = n0 + 8 * j + 2 * tq + zz;
                int lc = lblCol[c];
                float mn = 1e9f, mx = -1e9f;
#pragma unroll
                for (int i = 0; i < 2; i++) {
#pragma unroll
                    for (int h = 0; h < 2; h++) {
                        float s = acc[i][j][2 * h + zz];
                        int lr = lblRow[m0 + 16 * i + q + 8 * h];
                        if (lr == lc) { if (s < mn) mn = s; }
                        else if (s > mx) mx = s;
                    }
                }
                cmnS[c * 33 + widx] = mn;
                cmxS[c * 33 + widx] = mx;
            }
        }
    }
    __syncthreads();

    if (!diag) {
        if (tid < 128) {
            float m = 1e9f;
#pragma unroll
            for (int w2 = 0; w2 < 32; w2++) m = fminf(m, cmnS[tid * 33 + w2]);
            atomicMin(&g_minpos[col0 + tid], fenc(m));
        } else if (tid < 256) {
            int c = tid - 128;
            float M = -1e9f;
#pragma unroll
            for (int w2 = 0; w2 < 32; w2++) M = fmaxf(M, cmxS[c * 33 + w2]);
            atomicMax(&g_maxneg[col0 + c], fenc(M));
        }
    }

    // coalesced S store
#pragma unroll
    for (int k = 0; k < 8; k++) {
        int r = wid + 16 * k;
        float4 v = *(float4*)&stage[r * SLD2 + lane * 4];
        *(float4*)(g_S + (size_t)(row0 + r) * N + col0 + lane * 4) = v;
    }
}

// ---------------- k_tsum: cp.async 4-slot ring, barrier-free self-consume ----------------
__global__ __launch_bounds__(512, 2) void k_tsum(int N) {
    extern __shared__ float4 ring[];               // 4*16*33 float4 = 33.8KB dynamic
    __shared__ int lR[128];
    __shared__ float rPth[128], rNth[128];
    __shared__ int lC[128];
    __shared__ float cPthS[128], cNthS[128];
    __shared__ float scP[16][132], scN[16][132];   // col partials per warp

    int tid = threadIdx.x;
    int bx, by;
    tri_map(blockIdx.x, bx, by);
    int row0 = by * 128, col0 = bx * 128;
    bool diag = (bx == by);

    if (tid < 128) {
        lR[tid]   = g_lab[row0 + tid];
        rPth[tid] = fdec(g_maxneg[row0 + tid]) + MARGIN;
        rNth[tid] = fdec(g_minpos[row0 + tid]) - MARGIN;
    } else if (tid < 256) {
        int c = tid - 128;
        lC[c]    = g_lab[col0 + c];
        cPthS[c] = fdec(g_maxneg[col0 + c]) + MARGIN;
        cNthS[c] = fdec(g_minpos[col0 + c]) - MARGIN;
    }
    __syncthreads();

    int lane = tid & 31, w = tid >> 5;     // 16 warps; warp w handles rows w+16k
    int cbase = 4 * lane;
    uint32_t ringB = smem_u32(ring);
    // per-thread fixed ring offset within a slot: (w*33 + lane) float4
    uint32_t myOff = (uint32_t)(w * 33 + lane) * 16u;
    const char* srcBase = (const char*)(g_S + (size_t)(row0 + w) * N + col0 + cbase);
    size_t srcStride = (size_t)16 * N * 4;   // 16 rows

    // hoist per-lane column data to registers
    int   lc[4];
    float cpth[4], cnth[4];
#pragma unroll
    for (int z = 0; z < 4; z++) {
        lc[z]   = lC[cbase + z];
        cpth[z] = cPthS[cbase + z];
        cnth[z] = cNthS[cbase + z];
    }
    float cP[4] = {0.f, 0.f, 0.f, 0.f}, cN[4] = {0.f, 0.f, 0.f, 0.f};

#define TS_ISSUE(K) do {                                                   \
        CP_ASYNC16(ringB + (uint32_t)(((K) & 3) * 16 * 33) * 16u + myOff,  \
                   srcBase + (size_t)(K) * srcStride);                     \
        CP_COMMIT();                                                       \
    } while (0)

    TS_ISSUE(0); TS_ISSUE(1); TS_ISSUE(2); TS_ISSUE(3);

#define TS_PROC(K) do {                                                            \
        int r = w + 16 * (K);                                                      \
        float4 v = ring[((K) & 3) * 16 * 33 + w * 33 + lane];                      \
        int lr = lR[r];                                                            \
        float rpt = rPth[r], rnt = rNth[r];                                        \
        float rp = 0.f, rn = 0.f;                                                  \
        float sv[4] = {v.x, v.y, v.z, v.w};                                        \
        _Pragma("unroll")                                                          \
        for (int z = 0; z < 4; z++) {                                              \
            float s = sv[z];                                                       \
            if (lc[z] == lr) {                                                     \
                if (!(diag && r == cbase + z)) {                                   \
                    bool c1 = (s < rpt);                                           \
                    bool c2 = (!diag) && (s < cpth[z]);                            \
                    if (c1 | c2) {                                                 \
                        float e = __expf(-POS_W * (s - THRESH));                   \
                        if (c1) rp += e;                                           \
                        if (c2) cP[z] += e;                                        \
                    }                                                              \
                }                                                                  \
            } else {                                                               \
                bool c1 = (s > rnt);                                               \
                bool c2 = (!diag) && (s > cnth[z]);                                \
                if (c1 | c2) {                                                     \
                    float e = __expf(NEG_W * (s - THRESH));                        \
                    if (c1) rn += e;                                               \
                    if (c2) cN[z] += e;                                            \
                }                                                                  \
            }                                                                      \
        }                                                                          \
        _Pragma("unroll")                                                          \
        for (int o = 16; o > 0; o >>= 1) {                                         \
            rp += __shfl_xor_sync(0xffffffffu, rp, o);                             \
            rn += __shfl_xor_sync(0xffffffffu, rn, o);                             \
        }                                                                          \
        if (lane == 0) {                                                           \
            atomicAdd(&g_psum[row0 + r], rp);                                      \
            atomicAdd(&g_nsum[row0 + r], rn);                                      \
        }                                                                          \
    } while (0)

    cp_wait<3>(); TS_PROC(0); TS_ISSUE(4);
    cp_wait<3>(); TS_PROC(1); TS_ISSUE(5);
    cp_wait<3>(); TS_PROC(2); TS_ISSUE(6);
    cp_wait<3>(); TS_PROC(3); TS_ISSUE(7);
    cp_wait<3>(); TS_PROC(4);
    cp_wait<2>(); TS_PROC(5);
    cp_wait<1>(); TS_PROC(6);
    cp_wait<0>(); TS_PROC(7);

#undef TS_ISSUE
#undef TS_PROC

    if (!diag) {
#pragma unroll
        for (int z = 0; z < 4; z++) {
            scP[w][cbase + z] = cP[z];
            scN[w][cbase + z] = cN[z];
        }
        __syncthreads();
        if (tid < 128) {
            float colP = 0.f;
#pragma unroll
            for (int w2 = 0; w2 < 16; w2++) colP += scP[w2][tid];
            atomicAdd(&g_psum[col0 + tid], colP);
        } else if (tid < 256) {
            int c = tid - 128;
            float colN = 0.f;
#pragma unroll
            for (int w2 = 0; w2 < 16; w2++) colN += scN[w2][c];
            atomicAdd(&g_nsum[col0 + c], colN);
        }
    }
}

// ---------------- k_final ----------------
__global__ void k_final(float* out, int out_size, int N) {
    __shared__ float sp[256], sn[256], sc[256];
    int t = threadIdx.x;
    float pt = 0.f, nt = 0.f, ct = 0.f;
    for (int i = t; i < N; i += 256) {
        float mp  = fdec(g_minpos[i]);
        float mxn = fdec(g_maxneg[i]);
        float ps = g_psum[i], ns = g_nsum[i];
        bool valid = (mp < 5e8f) && (mxn > -5e8f) && (ps > 0.f) && (ns > 0.f);
        if (valid) {
            pt += log1pf(ps) * (1.0f / POS_W);
            nt += log1pf(ns) * (1.0f / NEG_W);
            ct += 1.f;
        }
    }
    sp[t] = pt; sn[t] = nt; sc[t] = ct;
    __syncthreads();
    for (int o = 128; o > 0; o >>= 1) {
        if (t < o) { sp[t] += sp[t + o]; sn[t] += sn[t + o]; sc[t] += sc[t + o]; }
        __syncthreads();
    }
    if (t == 0) {
        float cnt = fmaxf(sc[0], 1.f);
        float pm = sp[0] / cnt, nm = sn[0] / cnt;
        out[0] = pm + nm;
        if (out_size > 1) out[1] = pm;
        if (out_size > 2) out[2] = nm;
        for (int z = 3; z < out_size; z++) out[z] = 0.f;
    }
}

// ---------------- launch ----------------
extern "C" void kernel_launch(void* const* d_in, const int* in_sizes, int n_in,
                              void* d_out, int out_size) {
    const float* batch = (const float*)d_in[0];
    const void*  lab   = d_in[1];
    int N = in_sizes[1];
    if (N > NMAX) N = NMAX;

    static bool attr_done = false;
    if (!attr_done) {
        cudaFuncSetAttribute(k_gemm_mma, cudaFuncAttributeMaxDynamicSharedMemorySize,
                             SMEM_TOTAL);
        cudaFuncSetAttribute(k_tsum, cudaFuncAttributeMaxDynamicSharedMemorySize,
                             TS_RING_BYTES);
        attr_done = true;
    }

    k_detect<<<1, 256>>>((const int*)lab, N);
    k_prepnorm<<<(N + 7) / 8, 256>>>(batch, lab, N);
    int nb = N / 128;
    int ntiles = nb * (nb + 1) / 2;
    k_gemm_mma<<<ntiles, 512, SMEM_TOTAL>>>(N);
    k_tsum<<<ntiles, 512, TS_RING_BYTES>>>(N);
    k_final<<<1, 256>>>((float*)d_out, out_size, N);
}

// round 17
// speedup vs baseline: 1.1366x; 1.1366x over previous
#include <cuda_runtime.h>
#include <cuda_fp16.h>
#include <cstdint>
#include <cstddef>
#include <math.h>

#define NMAX 4096
#define DDIM 128
#define POS_W 2.0f
#define NEG_W 40.0f
#define MARGIN 0.1f
#define THRESH 0.5f

// ---------------- scratch (no allocations allowed) ----------------
__device__ unsigned short g_xhi[NMAX * DDIM];          // fp16 rows
__device__ int      g_lab[NMAX];
__device__ float    g_S[(size_t)NMAX * NMAX];          // upper-triangle tiles only
__device__ unsigned g_minpos[NMAX];
__device__ unsigned g_maxneg[NMAX];
__device__ float    g_psum[NMAX];
__device__ float    g_nsum[NMAX];
__device__ int      g_lflag;

__device__ __forceinline__ unsigned fenc(float f) {
    unsigned u = __float_as_uint(f);
    return (u & 0x80000000u) ? ~u : (u | 0x80000000u);
}
__device__ __forceinline__ float fdec(unsigned e) {
    unsigned u = (e & 0x80000000u) ? (e ^ 0x80000000u) : ~e;
    return __uint_as_float(u);
}

__device__ __forceinline__ uint32_t smem_u32(const void* p) {
    uint32_t a;
    asm("{ .reg .u64 t; cvta.to.shared.u64 t, %1; cvt.u32.u64 %0, t; }" : "=r"(a) : "l"(p));
    return a;
}

#define LDSM_X4(r, ad) \
    asm volatile("ldmatrix.sync.aligned.m8n8.x4.shared.b16 {%0,%1,%2,%3}, [%4];" \
        : "=r"((r)[0]), "=r"((r)[1]), "=r"((r)[2]), "=r"((r)[3]) : "r"(ad))

#define MMAF16(c, a, b) \
    asm volatile("mma.sync.aligned.m16n8k16.row.col.f32.f16.f16.f32 " \
        "{%0,%1,%2,%3}, {%4,%5,%6,%7}, {%8,%9}, {%0,%1,%2,%3};" \
        : "+f"((c)[0]), "+f"((c)[1]), "+f"((c)[2]), "+f"((c)[3]) \
        : "r"((a)[0]), "r"((a)[1]), "r"((a)[2]), "r"((a)[3]), "r"((b)[0]), "r"((b)[1]))

#define CP_ASYNC16(sa, ga) \
    asm volatile("cp.async.cg.shared.global [%0], [%1], 16;" :: "r"(sa), "l"(ga))
#define CP_COMMIT() asm volatile("cp.async.commit_group;" ::: "memory")
#define CP_WAIT0()  asm volatile("cp.async.wait_group 0;" ::: "memory")

template <int P>
__device__ __forceinline__ void cp_wait() {
    asm volatile("cp.async.wait_group %0;" :: "n"(P) : "memory");
}

// smem layout (bytes). 2 fp16 tiles [128][136] (272B stride, ldmatrix conflict-free)
#define TLD       136
#define TILE_B    (128 * TLD * 2)
#define OFF_LBLR  0
#define OFF_LBLC  512
#define OFF_AHI   1024
#define OFF_BHI   (OFF_AHI + TILE_B)
// epilogue overlays (on dead tiles + beyond): stage 67.6KB + col scoreboards
#define SLD2      132
#define OFF_STAGE OFF_AHI
#define OFF_CMN   (OFF_STAGE + 128 * SLD2 * 4)
#define OFF_CMX   (OFF_CMN + 128 * 33 * 4)
#define SMEM_TOTAL (OFF_CMX + 128 * 33 * 4)   // 102400 > tiles end (70656)

// k_tsum ring: 4 slots x 16 rows x 33 float4 (528B row stride)
#define TS_RING_BYTES (4 * 16 * 33 * 16)

__device__ __forceinline__ uint32_t pack2h(float x, float y) {
    __half hx = __float2half_rn(x), hy = __float2half_rn(y);
    unsigned short a = *(unsigned short*)&hx, b = *(unsigned short*)&hy;
    return (uint32_t)a | ((uint32_t)b << 16);
}

__device__ __forceinline__ void tri_map(int t, int& bx, int& by) {
    bx = (int)((sqrtf(8.0f * (float)t + 1.0f) - 1.0f) * 0.5f);
    while ((bx + 1) * (bx + 2) / 2 <= t) bx++;
    while (bx * (bx + 1) / 2 > t) bx--;
    by = t - bx * (bx + 1) / 2;
}

// ---------------- small kernels ----------------
__global__ void k_detect(const int* __restrict__ lab32, int N) {
    __shared__ int s;
    if (threadIdx.x == 0) s = 0;
    __syncthreads();
    int any = 0;
    for (int i = 1 + 2 * (int)threadIdx.x; i < N; i += 2 * (int)blockDim.x)
        if (lab32[i] != 0) any = 1;
    if (any) atomicOr(&s, 1);
    __syncthreads();
    if (threadIdx.x == 0) g_lflag = s;
}

// fused: per-row L2 norm + fp16 convert, plus label convert + per-row init
__global__ void k_prepnorm(const float* __restrict__ x, const void* __restrict__ labv, int N) {
    int warp = threadIdx.x >> 5, lane = threadIdx.x & 31;
    if (threadIdx.x < 8) {
        int i = blockIdx.x * 8 + threadIdx.x;
        if (i < N) {
            int v;
            if (g_lflag) v = ((const int*)labv)[i];
            else         v = (int)(((const long long*)labv)[i]);
            g_lab[i]    = v;
            g_minpos[i] = fenc(1e9f);
            g_maxneg[i] = fenc(-1e9f);
            g_psum[i]   = 0.f;
            g_nsum[i]   = 0.f;
        }
    }
    int row = blockIdx.x * 8 + warp;
    if (row >= N) return;
    float4 v = *(const float4*)(x + (size_t)row * DDIM + lane * 4);
    float ss = v.x * v.x + v.y * v.y + v.z * v.z + v.w * v.w;
#pragma unroll
    for (int o = 16; o > 0; o >>= 1) ss += __shfl_xor_sync(0xffffffffu, ss, o);
    float inv = 1.0f / sqrtf(ss);
    uint32_t h0 = pack2h(v.x * inv, v.y * inv);
    uint32_t h1 = pack2h(v.z * inv, v.w * inv);
    *(uint2*)(g_xhi + (size_t)row * DDIM + lane * 4) = make_uint2(h0, h1);
}

// ---------------- HMMA tile kernel: plain fp16 (hh only) ----------------
__global__ __launch_bounds__(512, 1) void k_gemm_mma(int N) {
    extern __shared__ char smem[];
    uint32_t sb = smem_u32(smem);
    int* lblRow = (int*)(smem + OFF_LBLR);
    int* lblCol = (int*)(smem + OFF_LBLC);

    int tid = threadIdx.x, wid = tid >> 5, lane = tid & 31;

    int bx, by;
    tri_map(blockIdx.x, bx, by);
    int row0 = by * 128, col0 = bx * 128;
    bool diag = (bx == by);

    if (tid < 128) lblRow[tid] = g_lab[row0 + tid];
    else if (tid < 256) lblCol[tid - 128] = g_lab[col0 + tid - 128];

    // prologue: cp.async copies of the fp16 tiles
    {
        int r = tid >> 2, ch = (tid & 3) * 32;
#pragma unroll
        for (int qq = 0; qq < 4; qq++) {
            int col = ch + qq * 8;
            uint32_t off = (uint32_t)(r * TLD + col) * 2u;
            CP_ASYNC16(sb + OFF_AHI + off, (const char*)(g_xhi + (size_t)(row0 + r) * DDIM + col));
            CP_ASYNC16(sb + OFF_BHI + off, (const char*)(g_xhi + (size_t)(col0 + r) * DDIM + col));
        }
        CP_COMMIT();
        CP_WAIT0();
    }
    __syncthreads();

    // 16 warps -> 4 (m) x 4 (n); warp tile 32x32
    int warp_m = wid >> 2, warp_n = wid & 3;
    int m0 = warp_m * 32, n0 = warp_n * 32;
    int q = lane >> 2, tq = lane & 3;

    float acc[2][4][4];
#pragma unroll
    for (int i = 0; i < 2; i++)
#pragma unroll
        for (int j = 0; j < 4; j++)
#pragma unroll
            for (int r = 0; r < 4; r++) acc[i][j][r] = 0.f;

    int aRow = (lane & 7) + ((lane >> 3) & 1) * 8;
    int aColH = ((lane >> 4) & 1) * 8;
    int bRow = (lane & 7) + ((lane >> 4) & 1) * 8;
    int bColH = ((lane >> 3) & 1) * 8;

    uint32_t aHi = sb + OFF_AHI + (uint32_t)((m0 + aRow) * TLD + aColH) * 2u;
    uint32_t bHi = sb + OFF_BHI + (uint32_t)((n0 + bRow) * TLD + bColH) * 2u;

    uint32_t ah[2][8], bh[2][8];

#define LOAD_STEP(B, K0) do {                                             \
        uint32_t ko = (uint32_t)(K0) * 2u;                                \
        LDSM_X4(&ah[B][0], aHi + ko);                                     \
        LDSM_X4(&ah[B][4], aHi + (uint32_t)(16 * TLD) * 2u + ko);         \
        LDSM_X4(&bh[B][0], bHi + ko);                                     \
        LDSM_X4(&bh[B][4], bHi + (uint32_t)(16 * TLD) * 2u + ko);         \
    } while (0)

    LOAD_STEP(0, 0);
#pragma unroll
    for (int s = 0; s < 8; s++) {
        int buf = s & 1;
        if (s < 7) {
            if (buf == 0) LOAD_STEP(1, (s + 1) * 16);
            else          LOAD_STEP(0, (s + 1) * 16);
        }
#pragma unroll
        for (int i = 0; i < 2; i++)
#pragma unroll
            for (int j = 0; j < 4; j++)
                MMAF16(acc[i][j], &ah[buf][4 * i], &bh[buf][2 * j]);
    }
#undef LOAD_STEP

    // ---- row stats from accumulators ----
#pragma unroll
    for (int i = 0; i < 2; i++) {
#pragma unroll
        for (int h = 0; h < 2; h++) {
            int rl = m0 + 16 * i + q + 8 * h;
            int gr = row0 + rl;
            int lr = lblRow[rl];
            float mn = 1e9f, mx = -1e9f;
#pragma unroll
            for (int j = 0; j < 4; j++) {
#pragma unroll
                for (int zz = 0; zz < 2; zz++) {
                    float s = acc[i][j][2 * h + zz];
                    int c = n0 + 8 * j + 2 * tq + zz;
                    if (lblCol[c] == lr) {
                        if (gr != col0 + c && s < mn) mn = s;
                    } else if (s > mx) mx = s;
                }
            }
            mn = fminf(mn, __shfl_xor_sync(0xffffffffu, mn, 1));
            mx = fmaxf(mx, __shfl_xor_sync(0xffffffffu, mx, 1));
            mn = fminf(mn, __shfl_xor_sync(0xffffffffu, mn, 2));
            mx = fmaxf(mx, __shfl_xor_sync(0xffffffffu, mx, 2));
            if (tq == 0) {
                atomicMin(&g_minpos[gr], fenc(mn));
                atomicMax(&g_maxneg[gr], fenc(mx));
            }
        }
    }

    // ---- overlay epilogue: stage S + col-stat scoreboards over dead tiles ----
    __syncthreads();
    float* stage = (float*)(smem + OFF_STAGE);
    float* cmnS  = (float*)(smem + OFF_CMN);
    float* cmxS  = (float*)(smem + OFF_CMX);

#pragma unroll
    for (int i = 0; i < 2; i++) {
#pragma unroll
        for (int j = 0; j < 4; j++) {
#pragma unroll
            for (int h = 0; h < 2; h++) {
                int r = m0 + 16 * i + q + 8 * h;
                int c = n0 + 8 * j + 2 * tq;
                *(float2*)&stage[r * SLD2 + c] =
                    make_float2(acc[i][j][2 * h], acc[i][j][2 * h + 1]);
            }
        }
    }
    if (!diag) {
        int widx = warp_m * 8 + q;
#pragma unroll
        for (int j = 0; j < 4; j++) {
#pragma unroll
            for (int zz = 0; zz < 2; zz++) {
                int c = n0 + 8 * j + 2 * tq + zz;
                int lc = lblCol[c];
                float mn = 1e9f, mx = -1e9f;
#pragma unroll
                for (int i = 0; i < 2; i++) {
#pragma unroll
                    for (int h = 0; h < 2; h++) {
                        float s = acc[i][j][2 * h + zz];
                        int lr = lblRow[m0 + 16 * i + q + 8 * h];
                        if (lr == lc) { if (s < mn) mn = s; }
                        else if (s > mx) mx = s;
                    }
                }
                cmnS[c * 33 + widx] = mn;
                cmxS[c * 33 + widx] = mx;
            }
        }
    }
    __syncthreads();

    if (!diag) {
        if (tid < 128) {
            float m = 1e9f;
#pragma unroll
            for (int w2 = 0; w2 < 32; w2++) m = fminf(m, cmnS[tid * 33 + w2]);
            atomicMin(&g_minpos[col0 + tid], fenc(m));
        } else if (tid < 256) {
            int c = tid - 128;
            float M = -1e9f;
#pragma unroll
            for (int w2 = 0; w2 < 32; w2++) M = fmaxf(M, cmxS[c * 33 + w2]);
            atomicMax(&g_maxneg[col0 + c], fenc(M));
        }
    }

    // coalesced S store
#pragma unroll
    for (int k = 0; k < 8; k++) {
        int r = wid + 16 * k;
        float4 v = *(float4*)&stage[r * SLD2 + lane * 4];
        *(float4*)(g_S + (size_t)(row0 + r) * N + col0 + lane * 4) = v;
    }
}

// ---------------- k_tsum: cp.async 4-slot ring, barrier-free self-consume ----------------
__global__ __launch_bounds__(512, 2) void k_tsum(int N) {
    extern __shared__ float4 ring[];               // 4*16*33 float4 = 33.8KB dynamic
    __shared__ int lR[128];
    __shared__ float rPth[128], rNth[128];
    __shared__ int lC[128];
    __shared__ float cPthS[128], cNthS[128];
    __shared__ float scP[16][132], scN[16][132];   // col partials per warp

    int tid = threadIdx.x;
    int bx, by;
    tri_map(blockIdx.x, bx, by);
    int row0 = by * 128, col0 = bx * 128;
    bool diag = (bx == by);

    if (tid < 128) {
        lR[tid]   = g_lab[row0 + tid];
        rPth[tid] = fdec(g_maxneg[row0 + tid]) + MARGIN;
        rNth[tid] = fdec(g_minpos[row0 + tid]) - MARGIN;
    } else if (tid < 256) {
        int c = tid - 128;
        lC[c]    = g_lab[col0 + c];
        cPthS[c] = fdec(g_maxneg[col0 + c]) + MARGIN;
        cNthS[c] = fdec(g_minpos[col0 + c]) - MARGIN;
    }
    __syncthreads();

    int lane = tid & 31, w = tid >> 5;     // 16 warps; warp w handles rows w+16k
    int cbase = 4 * lane;
    uint32_t ringB = smem_u32(ring);
    uint32_t myOff = (uint32_t)(w * 33 + lane) * 16u;
    const char* srcBase = (const char*)(g_S + (size_t)(row0 + w) * N + col0 + cbase);
    size_t srcStride = (size_t)16 * N * 4;

    int   lc[4];
    float cpth[4], cnth[4];
#pragma unroll
    for (int z = 0; z < 4; z++) {
        lc[z]   = lC[cbase + z];
        cpth[z] = cPthS[cbase + z];
        cnth[z] = cNthS[cbase + z];
    }
    float cP[4] = {0.f, 0.f, 0.f, 0.f}, cN[4] = {0.f, 0.f, 0.f, 0.f};

#define TS_ISSUE(K) do {                                                   \
        CP_ASYNC16(ringB + (uint32_t)(((K) & 3) * 16 * 33) * 16u + myOff,  \
                   srcBase + (size_t)(K) * srcStride);                     \
        CP_COMMIT();                                                       \
    } while (0)

    TS_ISSUE(0); TS_ISSUE(1); TS_ISSUE(2); TS_ISSUE(3);

#define TS_PROC(K) do {                                                            \
        int r = w + 16 * (K);                                                      \
        float4 v = ring[((K) & 3) * 16 * 33 + w * 33 + lane];                      \
        int lr = lR[r];                                                            \
        float rpt = rPth[r], rnt = rNth[r];                                        \
        float rp = 0.f, rn = 0.f;                                                  \
        float sv[4] = {v.x, v.y, v.z, v.w};                                        \
        _Pragma("unroll")                                                          \
        for (int z = 0; z < 4; z++) {                                              \
            float s = sv[z];                                                       \
            if (lc[z] == lr) {                                                     \
                if (!(diag && r == cbase + z)) {                                   \
                    bool c1 = (s < rpt);                                           \
                    bool c2 = (!diag) && (s < cpth[z]);                            \
                    if (c1 | c2) {                                                 \
                        float e = __expf(-POS_W * (s - THRESH));                   \
                        if (c1) rp += e;                                           \
                        if (c2) cP[z] += e;                                        \
                    }                                                              \
                }                                                                  \
            } else {                                                               \
                bool c1 = (s > rnt);                                               \
                bool c2 = (!diag) && (s > cnth[z]);                                \
                if (c1 | c2) {                                                     \
                    float e = __expf(NEG_W * (s - THRESH));                        \
                    if (c1) rn += e;                                               \
                    if (c2) cN[z] += e;                                            \
                }                                                                  \
            }                                                                      \
        }                                                                          \
        _Pragma("unroll")                                                          \
        for (int o = 16; o > 0; o >>= 1) {                                         \
            rp += __shfl_xor_sync(0xffffffffu, rp, o);                             \
            rn += __shfl_xor_sync(0xffffffffu, rn, o);                             \
        }                                                                          \
        if (lane == 0) {                                                           \
            atomicAdd(&g_psum[row0 + r], rp);                                      \
            atomicAdd(&g_nsum[row0 + r], rn);                                      \
        }                                                                          \
    } while (0)

    cp_wait<3>(); TS_PROC(0); TS_ISSUE(4);
    cp_wait<3>(); TS_PROC(1); TS_ISSUE(5);
    cp_wait<3>(); TS_PROC(2); TS_ISSUE(6);
    cp_wait<3>(); TS_PROC(3); TS_ISSUE(7);
    cp_wait<3>(); TS_PROC(4);
    cp_wait<2>(); TS_PROC(5);
    cp_wait<1>(); TS_PROC(6);
    cp_wait<0>(); TS_PROC(7);

#undef TS_ISSUE
#undef TS_PROC

    if (!diag) {
#pragma unroll
        for (int z = 0; z < 4; z++) {
            scP[w][cbase + z] = cP[z];
            scN[w][cbase + z] = cN[z];
        }
        __syncthreads();
        if (tid < 128) {
            float colP = 0.f;
#pragma unroll
            for (int w2 = 0; w2 < 16; w2++) colP += scP[w2][tid];
            atomicAdd(&g_psum[col0 + tid], colP);
        } else if (tid < 256) {
            int c = tid - 128;
            float colN = 0.f;
#pragma unroll
            for (int w2 = 0; w2 < 16; w2++) colN += scN[w2][c];
            atomicAdd(&g_nsum[col0 + c], colN);
        }
    }
}

// ---------------- k_final ----------------
__global__ void k_final(float* out, int out_size, int N) {
    __shared__ float sp[256], sn[256], sc[256];
    int t = threadIdx.x;
    float pt = 0.f, nt = 0.f, ct = 0.f;
    for (int i = t; i < N; i += 256) {
        float mp  = fdec(g_minpos[i]);
        float mxn = fdec(g_maxneg[i]);
        float ps = g_psum[i], ns = g_nsum[i];
        bool valid = (mp < 5e8f) && (mxn > -5e8f) && (ps > 0.f) && (ns > 0.f);
        if (valid) {
            pt += log1pf(ps) * (1.0f / POS_W);
            nt += log1pf(ns) * (1.0f / NEG_W);
            ct += 1.f;
        }
    }
    sp[t] = pt; sn[t] = nt; sc[t] = ct;
    __syncthreads();
    for (int o = 128; o > 0; o >>= 1) {
        if (t < o) { sp[t] += sp[t + o]; sn[t] += sn[t + o]; sc[t] += sc[t + o]; }
        __syncthreads();
    }
    if (t == 0) {
        float cnt = fmaxf(sc[0], 1.f);
        float pm = sp[0] / cnt, nm = sn[0] / cnt;
        out[0] = pm + nm;
        if (out_size > 1) out[1] = pm;
        if (out_size > 2) out[2] = nm;
        for (int z = 3; z < out_size; z++) out[z] = 0.f;
    }
}

// ---------------- launch ----------------
extern "C" void kernel_launch(void* const* d_in, const int* in_sizes, int n_in,
                              void* d_out, int out_size) {
    const float* batch = (const float*)d_in[0];
    const void*  lab   = d_in[1];
    int N = in_sizes[1];
    if (N > NMAX) N = NMAX;

    static bool attr_done = false;
    if (!attr_done) {
        cudaFuncSetAttribute(k_gemm_mma, cudaFuncAttributeMaxDynamicSharedMemorySize,
                             SMEM_TOTAL);
        cudaFuncSetAttribute(k_tsum, cudaFuncAttributeMaxDynamicSharedMemorySize,
                             TS_RING_BYTES);
        attr_done = true;
    }

    k_detect<<<1, 256>>>((const int*)lab, N);
    k_prepnorm<<<(N + 7) / 8, 256>>>(batch, lab, N);
    int nb = N / 128;
    int ntiles = nb * (nb + 1) / 2;
    k_gemm_mma<<<ntiles, 512, SMEM_TOTAL>>>(N);
    k_tsum<<<ntiles, 512, TS_RING_BYTES>>>(N);
    k_final<<<1, 256>>>((float*)d_out, out_size, N);
}